// round 12
// baseline (speedup 1.0000x reference)
#include <cuda_runtime.h>
#include <cuda_bf16.h>
#include <cstdint>
#include <math.h>

// ---------------------------------------------------------------------------
// MS Deformable Attention — mma.sync tf32 GEMMs (sm_103 non-'a' toolchain:
// tcgen05 is NOT available; ptxas targets plain sm_103).
// ---------------------------------------------------------------------------

#define BS        8
#define LEN_Q     1024
#define EMBED     256
#define NHEAD     8
#define NLVL      4
#define NPTS      4
#define HEADDIM   32
#define LEN_V     13294
#define NQ_TOT    (BS * LEN_Q)          // 8192
#define MV_TOT    (BS * LEN_V)          // 106352
#define TPQ       (NHEAD * NLVL * NPTS) // 128

__device__ __constant__ int c_lvl_start[4] = {0, 10000, 12500, 13125};
__device__ __constant__ int c_lvl_hw[4]    = {100, 50, 25, 13};

__device__ float g_vproj[(size_t)MV_TOT * EMBED];
__device__ float g_locx[NQ_TOT * TPQ];
__device__ float g_locy[NQ_TOT * TPQ];
__device__ float g_wgt [NQ_TOT * TPQ];
__device__ float g_att [NQ_TOT * EMBED];
__device__ float g_wtf[2][EMBED * EMBED];   // [0]=vp_w, [1]=op_w pre-rounded to tf32

// ---------------------------------------------------------------------------
// tf32 helpers
// ---------------------------------------------------------------------------
__device__ __forceinline__ float f2tf(float x) {
    unsigned u;
    asm("cvt.rna.tf32.f32 %0, %1;" : "=r"(u) : "f"(x));
    return __uint_as_float(u);
}

__device__ __forceinline__ void mma_tf32(float c[4], const unsigned a[4], const unsigned b[2]) {
    asm volatile(
        "mma.sync.aligned.m16n8k8.row.col.f32.tf32.tf32.f32 "
        "{%0,%1,%2,%3}, {%4,%5,%6,%7}, {%8,%9}, {%0,%1,%2,%3};"
        : "+f"(c[0]), "+f"(c[1]), "+f"(c[2]), "+f"(c[3])
        : "r"(a[0]), "r"(a[1]), "r"(a[2]), "r"(a[3]), "r"(b[0]), "r"(b[1]));
}

__device__ __forceinline__ void cp_async16(void* smem_dst, const void* gptr) {
    unsigned d = (unsigned)__cvta_generic_to_shared(smem_dst);
    asm volatile("cp.async.cg.shared.global [%0], [%1], 16;" :: "r"(d), "l"(gptr));
}
#define CP_COMMIT() asm volatile("cp.async.commit_group;" ::: "memory")
#define CP_WAIT0()  asm volatile("cp.async.wait_group 0;" ::: "memory")

// ---------------------------------------------------------------------------
// Pre-round both weight matrices to tf32 in one launch.
// grid.x covers 2*EMBED*EMBED/256 blocks; W selected by high half.
// ---------------------------------------------------------------------------
__global__ __launch_bounds__(256) void round_w_kernel(const float* __restrict__ W0,
                                                      const float* __restrict__ W1,
                                                      float* __restrict__ O) {
    int i = blockIdx.x * 256 + threadIdx.x;
    const float* src = (i < EMBED * EMBED) ? W0 : (W1 - EMBED * EMBED);
    O[i] = f2tf(src[i]);
}

// ---------------------------------------------------------------------------
// tf32 tensor GEMM + bias: C[M,256] = A[M,256] @ Wtf[256,256] + bias
// BM=128 BN=128 BK=32, 256 threads = 8 warps (2x4), warp tile 64x32.
// A: LDG->cvt.rna->STS (producer-rounded). B: cp.async (pre-rounded W).
// As stride 36 (=4 mod 32), Bs stride 136 (=8 mod 32): conflict-free frags.
// Dynamic smem: 2*128*36*4 + 2*32*136*4 = 36864 + 34816 = 71680 B.
// ---------------------------------------------------------------------------
#define GEMM_SMEM 71680
__global__ __launch_bounds__(256) void gemm_tf32_kernel(
    const float* __restrict__ A, const float* __restrict__ Wtf,
    const float* __restrict__ bias, float* __restrict__ C, int M)
{
    extern __shared__ float sm[];
    float (*As)[128][36] = (float(*)[128][36])sm;                  // [buf][m][k]
    float (*Bs)[32][136] = (float(*)[32][136])(sm + 2 * 128 * 36); // [buf][k][n]

    const int tid  = threadIdx.x;
    const int w    = tid >> 5;
    const int lane = tid & 31;
    const int wm   = (w >> 2) * 64;
    const int wn   = (w & 3) * 32;
    const int tr   = lane >> 2;
    const int tc   = lane & 3;
    const int m0   = blockIdx.y * 128;
    const int n0   = blockIdx.x * 128;

    float4 ra[4];

    auto ldgA = [&](int c) {
#pragma unroll
        for (int i = 0; i < 4; i++) {
            int lin = tid + i * 256;
            int arow = lin >> 3, acol = (lin & 7) * 4;
            if (m0 + arow < M)
                ra[i] = *(const float4*)&A[(size_t)(m0 + arow) * 256 + c * 32 + acol];
            else
                ra[i] = make_float4(0.f, 0.f, 0.f, 0.f);
        }
    };
    auto cpB = [&](int c) {
#pragma unroll
        for (int i = 0; i < 4; i++) {
            int lin = tid + i * 256;
            int brow = lin >> 5, bcol = (lin & 31) * 4;
            cp_async16(&Bs[c & 1][brow][bcol],
                       &Wtf[(size_t)(c * 32 + brow) * 256 + n0 + bcol]);
        }
        CP_COMMIT();
    };
    auto stsA = [&](int c) {
#pragma unroll
        for (int i = 0; i < 4; i++) {
            int lin = tid + i * 256;
            int arow = lin >> 3, acol = (lin & 7) * 4;
            float4 v;
            v.x = f2tf(ra[i].x); v.y = f2tf(ra[i].y);
            v.z = f2tf(ra[i].z); v.w = f2tf(ra[i].w);
            *(float4*)&As[c & 1][arow][acol] = v;
        }
    };

    float acc[4][4][4] = {};

    auto compute = [&](int buf) {
#pragma unroll
        for (int kk = 0; kk < 4; kk++) {
            unsigned af[4][4], bf[4][2];
#pragma unroll
            for (int mi = 0; mi < 4; mi++) {
                int mr = wm + mi * 16 + tr;
                int kc = kk * 8 + tc;
                af[mi][0] = __float_as_uint(As[buf][mr    ][kc    ]);
                af[mi][1] = __float_as_uint(As[buf][mr + 8][kc    ]);
                af[mi][2] = __float_as_uint(As[buf][mr    ][kc + 4]);
                af[mi][3] = __float_as_uint(As[buf][mr + 8][kc + 4]);
            }
#pragma unroll
            for (int ni = 0; ni < 4; ni++) {
                int nc = wn + ni * 8 + tr;
                bf[ni][0] = __float_as_uint(Bs[buf][kk * 8 + tc    ][nc]);
                bf[ni][1] = __float_as_uint(Bs[buf][kk * 8 + tc + 4][nc]);
            }
#pragma unroll
            for (int mi = 0; mi < 4; mi++)
#pragma unroll
                for (int ni = 0; ni < 4; ni++)
                    mma_tf32(acc[mi][ni], af[mi], bf[ni]);
        }
    };

    // ---- prologue ----
    ldgA(0);
    cpB(0);
    stsA(0);
    CP_WAIT0();
    __syncthreads();

    // ---- mainloop: 8 chunks of K=32, 2-stage ----
#pragma unroll 1
    for (int c = 0; c < 8; c++) {
        if (c + 1 < 8) { ldgA(c + 1); cpB(c + 1); }
        compute(c & 1);
        if (c + 1 < 8) { stsA(c + 1); CP_WAIT0(); }
        __syncthreads();
    }

    // ---- epilogue ----
#pragma unroll
    for (int mi = 0; mi < 4; mi++) {
        int r0 = m0 + wm + mi * 16 + tr;
#pragma unroll
        for (int ni = 0; ni < 4; ni++) {
            int col = n0 + wn + ni * 8 + tc * 2;
            float bx = bias[col], by = bias[col + 1];
            if (r0 < M) {
                float2 o0 = make_float2(acc[mi][ni][0] + bx, acc[mi][ni][1] + by);
                *(float2*)&C[(size_t)r0 * 256 + col] = o0;
            }
            if (r0 + 8 < M) {
                float2 o1 = make_float2(acc[mi][ni][2] + bx, acc[mi][ni][3] + by);
                *(float2*)&C[(size_t)(r0 + 8) * 256 + col] = o1;
            }
        }
    }
}

// ---------------------------------------------------------------------------
// Fused so/aw projections + softmax + location prep
// ---------------------------------------------------------------------------
#define QB 8
__global__ __launch_bounds__(256) void samp_prep_kernel(
    const float* __restrict__ q, const float* __restrict__ ref,
    const float* __restrict__ so_w, const float* __restrict__ so_b,
    const float* __restrict__ aw_w, const float* __restrict__ aw_b)
{
    __shared__ float qs[QB][EMBED];
    __shared__ float sos[QB][EMBED];
    __shared__ float aws[QB][TPQ];

    const int tid = threadIdx.x;
    const int bq0 = blockIdx.x * QB;

    for (int i = tid; i < QB * EMBED; i += 256)
        qs[i >> 8][i & 255] = q[(size_t)(bq0 + (i >> 8)) * EMBED + (i & 255)];
    __syncthreads();

    const int j = tid;
    float accS[QB] = {};
    float accA[QB] = {};
    const bool hasA = (j < TPQ);
#pragma unroll 4
    for (int k = 0; k < EMBED; k++) {
        float w1 = so_w[k * EMBED + j];
        float w2 = hasA ? aw_w[k * TPQ + j] : 0.f;
#pragma unroll
        for (int qq = 0; qq < QB; qq++) {
            float s = qs[qq][k];
            accS[qq] = fmaf(s, w1, accS[qq]);
            accA[qq] = fmaf(s, w2, accA[qq]);
        }
    }
    float bS = so_b[j];
    float bA = hasA ? aw_b[j] : 0.f;
#pragma unroll
    for (int qq = 0; qq < QB; qq++) {
        sos[qq][j] = accS[qq] + bS;
        if (hasA) aws[qq][j] = accA[qq] + bA;
    }
    __syncthreads();

    if (tid < QB * NHEAD) {
        int qq = tid >> 3, h = tid & 7;
        float* a = &aws[qq][h * 16];
        float m = a[0];
#pragma unroll
        for (int i = 1; i < 16; i++) m = fmaxf(m, a[i]);
        float s = 0.f;
#pragma unroll
        for (int i = 0; i < 16; i++) { float e = __expf(a[i] - m); a[i] = e; s += e; }
        float inv = 1.f / s;
#pragma unroll
        for (int i = 0; i < 16; i++) a[i] *= inv;
    }
    __syncthreads();

    for (int it = tid; it < QB * TPQ; it += 256) {
        int qq = it >> 7;
        int t  = it & 127;
        int l  = (t >> 2) & 3;
        int bq = bq0 + qq;
        float rx = ref[((size_t)bq * NLVL + l) * 2 + 0];
        float ry = ref[((size_t)bq * NLVL + l) * 2 + 1];
        float sx = sos[qq][t * 2 + 0];
        float sy = sos[qq][t * 2 + 1];
        float wh = (float)c_lvl_hw[l];
        float lx = rx + sx / wh;
        float ly = ry + sy / wh;
        size_t o = (size_t)bq * TPQ + t;
        g_locx[o] = lx * wh - 0.5f;
        g_locy[o] = ly * wh - 0.5f;
        g_wgt[o]  = aws[qq][t];
    }
}

// ---------------------------------------------------------------------------
// Bilinear sampling + weighted accumulation
// ---------------------------------------------------------------------------
__global__ __launch_bounds__(256) void sample_kernel()
{
    const int bq   = blockIdx.x;
    const int h    = threadIdx.x >> 5;
    const int lane = threadIdx.x & 31;
    const int b    = bq >> 10;

    const float* vb = g_vproj + (size_t)b * LEN_V * EMBED;
    const int ch = h * HEADDIM + lane;
    const int base = bq * TPQ + h * 16;

    float acc = 0.f;
#pragma unroll
    for (int l = 0; l < NLVL; l++) {
        const int HW = c_lvl_hw[l];
        const float* vl = vb + (size_t)c_lvl_start[l] * EMBED;
#pragma unroll
        for (int p = 0; p < NPTS; p++) {
            int i = base + l * 4 + p;
            float x = g_locx[i], y = g_locy[i], wg = g_wgt[i];
            float x0f = floorf(x), y0f = floorf(y);
            int ix0 = (int)x0f, iy0 = (int)y0f;
            int ix1 = ix0 + 1, iy1 = iy0 + 1;
            float fx = x - x0f, fy = y - y0f;
            bool vx0 = (ix0 >= 0) & (ix0 < HW);
            bool vx1 = (ix1 >= 0) & (ix1 < HW);
            bool vy0 = (iy0 >= 0) & (iy0 < HW);
            bool vy1 = (iy1 >= 0) & (iy1 < HW);

            float v00 = (vx0 & vy0) ? vl[((size_t)(iy0 * HW + ix0)) * EMBED + ch] : 0.f;
            float v01 = (vx1 & vy0) ? vl[((size_t)(iy0 * HW + ix1)) * EMBED + ch] : 0.f;
            float v10 = (vx0 & vy1) ? vl[((size_t)(iy1 * HW + ix0)) * EMBED + ch] : 0.f;
            float v11 = (vx1 & vy1) ? vl[((size_t)(iy1 * HW + ix1)) * EMBED + ch] : 0.f;

            float top = fmaf(fx, v01 - v00, v00);
            float bot = fmaf(fx, v11 - v10, v10);
            float smp = fmaf(fy, bot - top, top);
            acc = fmaf(wg, smp, acc);
        }
    }
    g_att[(size_t)bq * EMBED + ch] = acc;
}

// ---------------------------------------------------------------------------
// Launch
// ---------------------------------------------------------------------------
extern "C" void kernel_launch(void* const* d_in, const int* in_sizes, int n_in,
                              void* d_out, int out_size)
{
    const float* query = (const float*)d_in[0];
    const float* refp  = (const float*)d_in[1];
    const float* value = (const float*)d_in[2];
    const float* so_w = (const float*)d_in[4];
    const float* so_b = (const float*)d_in[5];
    const float* aw_w = (const float*)d_in[6];
    const float* aw_b = (const float*)d_in[7];
    const float* vp_w = (const float*)d_in[8];
    const float* vp_b = (const float*)d_in[9];
    const float* op_w = (const float*)d_in[10];
    const float* op_b = (const float*)d_in[11];
    float* out = (float*)d_out;

    float *vproj_ptr, *att_ptr, *wtf_ptr;
    cudaGetSymbolAddress((void**)&vproj_ptr, g_vproj);
    cudaGetSymbolAddress((void**)&att_ptr,  g_att);
    cudaGetSymbolAddress((void**)&wtf_ptr,  g_wtf);

    cudaFuncSetAttribute(gemm_tf32_kernel,
                         cudaFuncAttributeMaxDynamicSharedMemorySize, GEMM_SMEM);

    // 0) pre-round both weight matrices to tf32 (one launch)
    round_w_kernel<<<2 * EMBED * EMBED / 256, 256>>>(vp_w, op_w, wtf_ptr);

    // 1) v projection: [106352,256] @ [256,256] + vp_b
    {
        dim3 grid(2, (MV_TOT + 127) / 128);   // (2, 831)
        gemm_tf32_kernel<<<grid, 256, GEMM_SMEM>>>(value, wtf_ptr, vp_b, vproj_ptr, MV_TOT);
    }
    // 2) sampling offsets / weights / locations
    samp_prep_kernel<<<NQ_TOT / QB, 256>>>(query, refp, so_w, so_b, aw_w, aw_b);
    // 3) bilinear sampling + weighted accumulation
    sample_kernel<<<NQ_TOT, 256>>>();
    // 4) output projection: [8192,256] @ [256,256] + op_b
    {
        dim3 grid(2, NQ_TOT / 128);           // (2, 64)
        gemm_tf32_kernel<<<grid, 256, GEMM_SMEM>>>(att_ptr, wtf_ptr + EMBED * EMBED, op_b, out, NQ_TOT);
    }
}

// round 13
// speedup vs baseline: 1.4768x; 1.4768x over previous
#include <cuda_runtime.h>
#include <cuda_bf16.h>
#include <cstdint>
#include <math.h>

// ---------------------------------------------------------------------------
// MS Deformable Attention — R5-proven tf32 GEMMs + offset-precomputed sampling
// ---------------------------------------------------------------------------

#define BS        8
#define LEN_Q     1024
#define EMBED     256
#define NHEAD     8
#define NLVL      4
#define NPTS      4
#define HEADDIM   32
#define LEN_V     13294
#define NQ_TOT    (BS * LEN_Q)          // 8192
#define MV_TOT    (BS * LEN_V)          // 106352
#define TPQ       (NHEAD * NLVL * NPTS) // 128

__device__ __constant__ int c_lvl_start[4] = {0, 10000, 12500, 13125};
__device__ __constant__ int c_lvl_hw[4]    = {100, 50, 25, 13};

__device__ float  g_vproj[(size_t)MV_TOT * EMBED];   // ~108.9 MB
__device__ int4   g_coff[NQ_TOT * TPQ];              // 4 corner element offsets
__device__ float4 g_cwgt[NQ_TOT * TPQ];              // 4 pre-multiplied weights
__device__ float  g_att [NQ_TOT * EMBED];

// ---------------------------------------------------------------------------
// tf32 helpers
// ---------------------------------------------------------------------------
__device__ __forceinline__ float f2tf(float x) {
    unsigned u;
    asm("cvt.rna.tf32.f32 %0, %1;" : "=r"(u) : "f"(x));
    return __uint_as_float(u);
}

__device__ __forceinline__ void mma_tf32(float c[4], const unsigned a[4], const unsigned b[2]) {
    asm volatile(
        "mma.sync.aligned.m16n8k8.row.col.f32.tf32.tf32.f32 "
        "{%0,%1,%2,%3}, {%4,%5,%6,%7}, {%8,%9}, {%0,%1,%2,%3};"
        : "+f"(c[0]), "+f"(c[1]), "+f"(c[2]), "+f"(c[3])
        : "r"(a[0]), "r"(a[1]), "r"(a[2]), "r"(a[3]), "r"(b[0]), "r"(b[1]));
}

// ---------------------------------------------------------------------------
// tf32 tensor GEMM + bias (R5-measured-good version, verbatim):
// C[M,256] = A[M,256] @ B[256,256] + bias
// BM=128, BN=128, BK=16. 256 threads = 8 warps (2x4), warp tile 64x32.
// Double-buffered SMEM; As stride 20, Bs stride 132.
// ---------------------------------------------------------------------------
#define GK 256
#define GN 256
__global__ __launch_bounds__(256) void gemm_tf32_kernel(
    const float* __restrict__ A, const float* __restrict__ B,
    const float* __restrict__ bias, float* __restrict__ C, int M)
{
    __shared__ float As[2][128][20];   // [m][k]
    __shared__ float Bs[2][16][132];   // [k][n]

    const int tid  = threadIdx.x;
    const int w    = tid >> 5;
    const int lane = tid & 31;
    const int wm   = (w >> 2) * 64;
    const int wn   = (w & 3) * 32;
    const int tr   = lane >> 2;
    const int tc   = lane & 3;
    const int m0   = blockIdx.y * 128;
    const int n0   = blockIdx.x * 128;

    float4 ra[2], rb[2];

    auto load_gmem = [&](int k0) {
#pragma unroll
        for (int i = 0; i < 2; i++) {
            int lin = tid + i * 256;
            int arow = lin >> 2, acol = (lin & 3) * 4;
            if (m0 + arow < M)
                ra[i] = *(const float4*)&A[(size_t)(m0 + arow) * GK + k0 + acol];
            else
                ra[i] = make_float4(0.f, 0.f, 0.f, 0.f);
            int brow = lin >> 5, bcol = (lin & 31) * 4;
            rb[i] = *(const float4*)&B[(size_t)(k0 + brow) * GN + n0 + bcol];
        }
    };

    auto store_smem = [&](int buf) {
#pragma unroll
        for (int i = 0; i < 2; i++) {
            int lin = tid + i * 256;
            int arow = lin >> 2, acol = (lin & 3) * 4;
            float4 va;
            va.x = f2tf(ra[i].x); va.y = f2tf(ra[i].y);
            va.z = f2tf(ra[i].z); va.w = f2tf(ra[i].w);
            *(float4*)&As[buf][arow][acol] = va;
            int brow = lin >> 5, bcol = (lin & 31) * 4;
            float4 vb;
            vb.x = f2tf(rb[i].x); vb.y = f2tf(rb[i].y);
            vb.z = f2tf(rb[i].z); vb.w = f2tf(rb[i].w);
            *(float4*)&Bs[buf][brow][bcol] = vb;
        }
    };

    float acc[4][4][4] = {};

    auto compute = [&](int buf) {
#pragma unroll
        for (int kk = 0; kk < 2; kk++) {
            unsigned af[4][4], bf[4][2];
#pragma unroll
            for (int mi = 0; mi < 4; mi++) {
                int mr = wm + mi * 16 + tr;
                int kc = kk * 8 + tc;
                af[mi][0] = __float_as_uint(As[buf][mr    ][kc    ]);
                af[mi][1] = __float_as_uint(As[buf][mr + 8][kc    ]);
                af[mi][2] = __float_as_uint(As[buf][mr    ][kc + 4]);
                af[mi][3] = __float_as_uint(As[buf][mr + 8][kc + 4]);
            }
#pragma unroll
            for (int ni = 0; ni < 4; ni++) {
                int nc = wn + ni * 8 + tr;
                bf[ni][0] = __float_as_uint(Bs[buf][kk * 8 + tc    ][nc]);
                bf[ni][1] = __float_as_uint(Bs[buf][kk * 8 + tc + 4][nc]);
            }
#pragma unroll
            for (int mi = 0; mi < 4; mi++)
#pragma unroll
                for (int ni = 0; ni < 4; ni++)
                    mma_tf32(acc[mi][ni], af[mi], bf[ni]);
        }
    };

    int buf = 0;
    load_gmem(0);
    store_smem(0);
    __syncthreads();
#pragma unroll 1
    for (int k0 = 16; k0 < GK; k0 += 16) {
        load_gmem(k0);
        compute(buf);
        store_smem(buf ^ 1);
        __syncthreads();
        buf ^= 1;
    }
    compute(buf);

#pragma unroll
    for (int mi = 0; mi < 4; mi++) {
        int r0 = m0 + wm + mi * 16 + tr;
#pragma unroll
        for (int ni = 0; ni < 4; ni++) {
            int col = n0 + wn + ni * 8 + tc * 2;
            float bx = bias[col], by = bias[col + 1];
            if (r0 < M) {
                float2 o0 = make_float2(acc[mi][ni][0] + bx, acc[mi][ni][1] + by);
                *(float2*)&C[(size_t)r0 * GN + col] = o0;
            }
            if (r0 + 8 < M) {
                float2 o1 = make_float2(acc[mi][ni][2] + bx, acc[mi][ni][3] + by);
                *(float2*)&C[(size_t)(r0 + 8) * GN + col] = o1;
            }
        }
    }
}

// ---------------------------------------------------------------------------
// Fused so/aw projections + softmax + corner offset/weight precompute.
// Each (query,point) computes its 4 corner offsets + pre-multiplied weights
// ONCE here (instead of 32x per warp in the sampling kernel).
// ---------------------------------------------------------------------------
#define QB 8
__global__ __launch_bounds__(256) void samp_prep_kernel(
    const float* __restrict__ q, const float* __restrict__ ref,
    const float* __restrict__ so_w, const float* __restrict__ so_b,
    const float* __restrict__ aw_w, const float* __restrict__ aw_b)
{
    __shared__ float qs[QB][EMBED];
    __shared__ float sos[QB][EMBED];
    __shared__ float aws[QB][TPQ];

    const int tid = threadIdx.x;
    const int bq0 = blockIdx.x * QB;

    for (int i = tid; i < QB * EMBED; i += 256)
        qs[i >> 8][i & 255] = q[(size_t)(bq0 + (i >> 8)) * EMBED + (i & 255)];
    __syncthreads();

    const int j = tid;
    float accS[QB] = {};
    float accA[QB] = {};
    const bool hasA = (j < TPQ);
#pragma unroll 4
    for (int k = 0; k < EMBED; k++) {
        float w1 = so_w[k * EMBED + j];
        float w2 = hasA ? aw_w[k * TPQ + j] : 0.f;
#pragma unroll
        for (int qq = 0; qq < QB; qq++) {
            float s = qs[qq][k];
            accS[qq] = fmaf(s, w1, accS[qq]);
            accA[qq] = fmaf(s, w2, accA[qq]);
        }
    }
    float bS = so_b[j];
    float bA = hasA ? aw_b[j] : 0.f;
#pragma unroll
    for (int qq = 0; qq < QB; qq++) {
        sos[qq][j] = accS[qq] + bS;
        if (hasA) aws[qq][j] = accA[qq] + bA;
    }
    __syncthreads();

    if (tid < QB * NHEAD) {
        int qq = tid >> 3, h = tid & 7;
        float* a = &aws[qq][h * 16];
        float m = a[0];
#pragma unroll
        for (int i = 1; i < 16; i++) m = fmaxf(m, a[i]);
        float s = 0.f;
#pragma unroll
        for (int i = 0; i < 16; i++) { float e = __expf(a[i] - m); a[i] = e; s += e; }
        float inv = 1.f / s;
#pragma unroll
        for (int i = 0; i < 16; i++) a[i] *= inv;
    }
    __syncthreads();

    // Corner offsets + weights: QB*128 items
    for (int it = tid; it < QB * TPQ; it += 256) {
        int qq = it >> 7;
        int t  = it & 127;
        int l  = (t >> 2) & 3;
        int bq = bq0 + qq;
        int b  = bq >> 10;

        float rx = ref[((size_t)bq * NLVL + l) * 2 + 0];
        float ry = ref[((size_t)bq * NLVL + l) * 2 + 1];
        float sx = sos[qq][t * 2 + 0];
        float sy = sos[qq][t * 2 + 1];
        int   W  = c_lvl_hw[l];
        float wh = (float)W;
        float x = (rx + sx / wh) * wh - 0.5f;     // pixel x (same math as R5)
        float y = (ry + sy / wh) * wh - 0.5f;     // pixel y

        float x0f = floorf(x), y0f = floorf(y);
        int ix0 = (int)x0f, iy0 = (int)y0f;
        float fx = x - x0f, fy = y - y0f;

        bool vx0 = (unsigned)ix0       < (unsigned)W;
        bool vx1 = (unsigned)(ix0 + 1) < (unsigned)W;
        bool vy0 = (unsigned)iy0       < (unsigned)W;
        bool vy1 = (unsigned)(iy0 + 1) < (unsigned)W;

        int base = b * LEN_V + c_lvl_start[l];
        int r0 = base + iy0 * W;
        int r1 = r0 + W;
        int o00 = (r0 + ix0)     << 8;   // *EMBED
        int o01 = (r0 + ix0 + 1) << 8;
        int o10 = (r1 + ix0)     << 8;
        int o11 = (r1 + ix0 + 1) << 8;

        float wg  = aws[qq][t];
        float wx0 = 1.f - fx, wy0 = 1.f - fy;
        float w00 = (vx0 & vy0) ? wg * wy0 * wx0 : 0.f;
        float w01 = (vx1 & vy0) ? wg * wy0 * fx  : 0.f;
        float w10 = (vx0 & vy1) ? wg * fy  * wx0 : 0.f;
        float w11 = (vx1 & vy1) ? wg * fy  * fx  : 0.f;
        if (!(vx0 & vy0)) o00 = 0;
        if (!(vx1 & vy0)) o01 = 0;
        if (!(vx0 & vy1)) o10 = 0;
        if (!(vx1 & vy1)) o11 = 0;

        size_t o = (size_t)bq * TPQ + t;
        g_coff[o] = make_int4(o00, o01, o10, o11);
        g_cwgt[o] = make_float4(w00, w01, w10, w11);
    }
}

// ---------------------------------------------------------------------------
// Sampling: block = (b,q); warp = head; lane = channel.
// All addressing precomputed: per point = 2 uniform loads + 4 gathers + 4 FMA.
// ---------------------------------------------------------------------------
__global__ __launch_bounds__(256) void sample_kernel()
{
    const int bq   = blockIdx.x;
    const int h    = threadIdx.x >> 5;
    const int lane = threadIdx.x & 31;
    const int ch   = h * HEADDIM + lane;

    const int4*   offp = &g_coff[bq * TPQ + h * 16];
    const float4* wp   = &g_cwgt[bq * TPQ + h * 16];

    float acc = 0.f;
#pragma unroll
    for (int p = 0; p < 16; p++) {
        int4   o = offp[p];   // warp-uniform (broadcast)
        float4 wv = wp[p];
        acc = fmaf(wv.x, __ldg(&g_vproj[o.x + ch]), acc);
        acc = fmaf(wv.y, __ldg(&g_vproj[o.y + ch]), acc);
        acc = fmaf(wv.z, __ldg(&g_vproj[o.z + ch]), acc);
        acc = fmaf(wv.w, __ldg(&g_vproj[o.w + ch]), acc);
    }
    g_att[(size_t)bq * EMBED + ch] = acc;
}

// ---------------------------------------------------------------------------
// Launch
// ---------------------------------------------------------------------------
extern "C" void kernel_launch(void* const* d_in, const int* in_sizes, int n_in,
                              void* d_out, int out_size)
{
    const float* query = (const float*)d_in[0];
    const float* refp  = (const float*)d_in[1];
    const float* value = (const float*)d_in[2];
    const float* so_w = (const float*)d_in[4];
    const float* so_b = (const float*)d_in[5];
    const float* aw_w = (const float*)d_in[6];
    const float* aw_b = (const float*)d_in[7];
    const float* vp_w = (const float*)d_in[8];
    const float* vp_b = (const float*)d_in[9];
    const float* op_w = (const float*)d_in[10];
    const float* op_b = (const float*)d_in[11];
    float* out = (float*)d_out;

    float *vproj_ptr, *att_ptr;
    cudaGetSymbolAddress((void**)&vproj_ptr, g_vproj);
    cudaGetSymbolAddress((void**)&att_ptr,  g_att);

    // 1) v projection: [106352,256] @ [256,256] + vp_b
    {
        dim3 grid(2, (MV_TOT + 127) / 128);   // (2, 831)
        gemm_tf32_kernel<<<grid, 256>>>(value, vp_w, vp_b, vproj_ptr, MV_TOT);
    }
    // 2) sampling offsets / weights / corner precompute
    samp_prep_kernel<<<NQ_TOT / QB, 256>>>(query, refp, so_w, so_b, aw_w, aw_b);
    // 3) bilinear sampling + weighted accumulation
    sample_kernel<<<NQ_TOT, 256>>>();
    // 4) output projection: [8192,256] @ [256,256] + op_b
    {
        dim3 grid(2, NQ_TOT / 128);           // (2, 64)
        gemm_tf32_kernel<<<grid, 256>>>(att_ptr, op_w, op_b, out, NQ_TOT);
    }
}